// round 15
// baseline (speedup 1.0000x reference)
#include <cuda_runtime.h>
#include <cuda_bf16.h>
#include <cstdint>

#define NU    200000
#define NI    100000
#define NTOT  300000
#define D     64
#define NNZ   3000000
#define BATCH 4096
#define EPS_P    0.1f
#define INV_TEMP 5.0f
#define CL_RATE  0.5
#define DECAY    1e-4

typedef unsigned long long ull;
typedef __nv_bfloat162 bf2;

#define NB_SCAN 293  // ceil(NTOT/1024)

// ---------------- persistent device scratch ----------------
__device__ bf2  g_bufE[NTOT * 32];
__device__ bf2  g_bufB[NTOT * 32];
__device__ bf2  g_bufC[NTOT * 32];
__device__ bf2  g_bufC2[NTOT * 32];
__device__ bf2  g_bufV1[NTOT * 32];
__device__ bf2  g_bufV2[NTOT * 32];
__device__ int  g_rowptr[NTOT + 1];
__device__ int  g_cnt[NTOT];
__device__ int  g_bsum[512];
__device__ int2 g_cv[NNZ];
// hop-2 row masking
__device__ unsigned char g_isb[NTOT];
__device__ int  g_mask[NTOT];
__device__ int  g_mpos[NTOT];
__device__ int  g_bsum2[512];
__device__ int  g_h2list[NTOT];
__device__ int  g_h2cnt;
// 0:accU 1:accP 2:accN 3:v1u 4:v1i 5:v2u 6:v2i
__device__ float g_acc[7][BATCH * D];
__device__ float g_ttl[2 * BATCH];
__device__ float g_posb[2 * BATCH];
__device__ double g_red[8];

// ---------------- Threefry-2x32-20 (JAX schedule) ----------------
__host__ __device__ __forceinline__ uint32_t rotl32(uint32_t x, int r) {
#ifdef __CUDA_ARCH__
  return __funnelshift_l(x, x, r);
#else
  return (x << r) | (x >> (32 - r));
#endif
}

__host__ __device__ __forceinline__ void tf2x32(uint32_t k0, uint32_t k1,
                                                uint32_t x0, uint32_t x1,
                                                uint32_t& o0, uint32_t& o1) {
  uint32_t ks2 = k0 ^ k1 ^ 0x1BD11BDAu;
  x0 += k0; x1 += k1;
#define TFR(r) { x0 += x1; x1 = rotl32(x1, r); x1 ^= x0; }
  TFR(13) TFR(15) TFR(26) TFR(6)
  x0 += k1;  x1 += ks2 + 1u;
  TFR(17) TFR(29) TFR(16) TFR(24)
  x0 += ks2; x1 += k0 + 2u;
  TFR(13) TFR(15) TFR(26) TFR(6)
  x0 += k0;  x1 += k1 + 3u;
  TFR(17) TFR(29) TFR(16) TFR(24)
  x0 += k1;  x1 += ks2 + 4u;
  TFR(13) TFR(15) TFR(26) TFR(6)
  x0 += ks2; x1 += k0 + 5u;
#undef TFR
  o0 = x0; o1 = x1;
}

__device__ __forceinline__ float tf_uniform(uint32_t k0, uint32_t k1, uint32_t j) {
  uint32_t a, b;
  tf2x32(k0, k1, 0u, j, a, b);
  uint32_t bits = a ^ b;
  return __uint_as_float((bits >> 9) | 0x3F800000u) - 1.0f;
}

__device__ __forceinline__ void apply_perturb(float& a0, float& a1,
                                              uint32_t k0, uint32_t k1,
                                              int row, int lane) {
  uint32_t j = (uint32_t)row * 64u + (uint32_t)(2 * lane);
  float u0 = tf_uniform(k0, k1, j);
  float u1 = tf_uniform(k0, k1, j + 1u);
  float ss = u0 * u0 + u1 * u1;
#pragma unroll
  for (int o = 16; o; o >>= 1) ss += __shfl_xor_sync(0xffffffffu, ss, o);
  float sc = EPS_P / fmaxf(sqrtf(ss), 1e-12f);
  float s0 = (a0 > 0.f ? 1.f : (a0 < 0.f ? -1.f : 0.f));
  float s1 = (a1 > 0.f ? 1.f : (a1 < 0.f ? -1.f : 0.f));
  a0 = fmaf(s0 * sc, u0, a0);
  a1 = fmaf(s1 * sc, u1, a1);
}

// ---------------- fast exp on FMA pipe ----------------
__device__ __forceinline__ float fast_exp(float x) {
  float y = x * 1.44269504088896341f;
  int ni = __float2int_rn(y);
  float f = y - (float)ni;
  float p = 0.0013333558146428443f;
  p = fmaf(p, f, 0.009618129107628477f);
  p = fmaf(p, f, 0.05550410866482158f);
  p = fmaf(p, f, 0.2402265069591007f);
  p = fmaf(p, f, 0.6931471805599453f);
  p = fmaf(p, f, 1.0f);
  float s = __int_as_float((ni + 127) << 23);
  return p * s;
}

__device__ __forceinline__ void fma_f32x2(ull& d, ull a, ull b) {
  asm("fma.rn.f32x2 %0, %1, %2, %0;" : "+l"(d) : "l"(a), "l"(b));
}

// warp-shuffle inclusive scan within a 1024-thread block.
__device__ __forceinline__ int block_incl_scan(int v, int t, int* sh32) {
  int lane = t & 31, wid = t >> 5;
#pragma unroll
  for (int o = 1; o < 32; o <<= 1) {
    int n = __shfl_up_sync(0xffffffffu, v, o);
    if (lane >= o) v += n;
  }
  if (lane == 31) sh32[wid] = v;
  __syncthreads();
  if (wid == 0) {
    int w = sh32[lane];
#pragma unroll
    for (int o = 1; o < 32; o <<= 1) {
      int n = __shfl_up_sync(0xffffffffu, w, o);
      if (lane >= o) w += n;
    }
    sh32[lane] = w;
  }
  __syncthreads();
  if (wid > 0) v += sh32[wid - 1];
  return v;
}

// ---------------- launch 1: convert ego0 + zero all state ----------------
__global__ void k_conv(const float* __restrict__ u, const float* __restrict__ it) {
  int i = blockIdx.x * blockDim.x + threadIdx.x;
  if (i < NTOT) { g_cnt[i] = 0; g_mask[i] = 0; g_isb[i] = 0; }
  if (i < 2 * BATCH) g_ttl[i] = 0.f;
  if (i < 8) g_red[i] = 0.0;
  if (i >= NTOT * 32) return;
  const float2* src = (i < NU * 32) ? ((const float2*)u + i)
                                    : ((const float2*)it + (i - NU * 32));
  g_bufE[i] = __float22bfloat162_rn(*src);
}

// ---------------- CSR count + batch-row marking ----------------
__global__ void k_count(const int* __restrict__ rows,
                        const int* __restrict__ users, const int* __restrict__ pos,
                        const int* __restrict__ neg) {
  int i = blockIdx.x * blockDim.x + threadIdx.x;
  if (i < NNZ) atomicAdd(&g_cnt[rows[i]], 1);
  if (i < BATCH) {
    int ru = __ldg(&users[i]);
    int rp = NU + __ldg(&pos[i]);
    int rn = NU + __ldg(&neg[i]);
    g_isb[ru] = 1; g_isb[rp] = 1; g_isb[rn] = 1;
    g_mask[ru] = 1; g_mask[rp] = 1; g_mask[rn] = 1;
  }
}

__global__ void k_scan1() {
  __shared__ int sh32[32];
  int gid = blockIdx.x * 1024 + threadIdx.x;
  int v = (gid < NTOT) ? g_cnt[gid] : 0;
  v = block_incl_scan(v, threadIdx.x, sh32);
  if (gid < NTOT) g_rowptr[gid + 1] = v;
  if (threadIdx.x == 1023) g_bsum[blockIdx.x] = v;
}

// fused scan2+scan3+cursor
__global__ void k_scan23() {
  __shared__ int sh[32];
  int t = threadIdx.x;
  int bid = blockIdx.x;
  int v = (t < bid && t < NB_SCAN) ? g_bsum[t] : 0;
#pragma unroll
  for (int o = 16; o; o >>= 1) v += __shfl_xor_sync(0xffffffffu, v, o);
  if ((t & 31) == 0) sh[t >> 5] = v;
  __syncthreads();
  if (t < 32) {
    int w = sh[t];
#pragma unroll
    for (int o = 16; o; o >>= 1) w += __shfl_xor_sync(0xffffffffu, w, o);
    if (t == 0) sh[0] = w;
  }
  __syncthreads();
  int pref = sh[0];
  int gid = bid * 1024 + t;
  if (gid < NTOT) {
    int cntv = g_cnt[gid];
    int rp_next = g_rowptr[gid + 1] + pref;
    g_rowptr[gid + 1] = rp_next;
    g_cnt[gid] = rp_next - cntv;  // cursor = row start
    if (gid == 0) g_rowptr[0] = 0;
  }
}

// scatter + neighbor marking (isb built in k_count)
__global__ void k_scatter(const int* __restrict__ rows, const int* __restrict__ cols,
                          const float* __restrict__ vals) {
  int i = blockIdx.x * blockDim.x + threadIdx.x;
  if (i >= NNZ) return;
  int r = rows[i];
  int c = cols[i];
  int p = atomicAdd(&g_cnt[r], 1);
  g_cv[p] = make_int2(c, __float_as_int(vals[i]));
  if (g_isb[r]) g_mask[c] = 1;
}

__global__ void k_mscan1() {
  __shared__ int sh32[32];
  int gid = blockIdx.x * 1024 + threadIdx.x;
  int v = (gid < NTOT) ? g_mask[gid] : 0;
  v = block_incl_scan(v, threadIdx.x, sh32);
  if (gid < NTOT) g_mpos[gid] = v;  // inclusive
  if (threadIdx.x == 1023) g_bsum2[blockIdx.x] = v;
}

// compact + total count (dual reduction: prefix + total)
__global__ void k_mcompact() {
  __shared__ int shp[32], sht[32];
  int t = threadIdx.x;
  int bid = blockIdx.x;
  int va = (t < NB_SCAN) ? g_bsum2[t] : 0;
  int vp = (t < bid) ? va : 0;
#pragma unroll
  for (int o = 16; o; o >>= 1) {
    va += __shfl_xor_sync(0xffffffffu, va, o);
    vp += __shfl_xor_sync(0xffffffffu, vp, o);
  }
  if ((t & 31) == 0) { shp[t >> 5] = vp; sht[t >> 5] = va; }
  __syncthreads();
  if (t < 32) {
    int wp = shp[t], wa = sht[t];
#pragma unroll
    for (int o = 16; o; o >>= 1) {
      wp += __shfl_xor_sync(0xffffffffu, wp, o);
      wa += __shfl_xor_sync(0xffffffffu, wa, o);
    }
    if (t == 0) { shp[0] = wp; sht[0] = wa; }
  }
  __syncthreads();
  int pref = shp[0];
  int gid = bid * 1024 + t;
  if (gid < NTOT && g_mask[gid])
    g_h2list[g_mpos[gid] - 1 + pref] = gid;
  if (bid == 0 && t == 0) g_h2cnt = sht[0];
}

// ---------------- SPMM core (single input, unroll 4 — proven) ----------------
__device__ __forceinline__ void spmm_row(const bf2* __restrict__ x,
                                         int w, int lane, float& a0, float& a1) {
  int s = g_rowptr[w], e = g_rowptr[w + 1];
  a0 = 0.f; a1 = 0.f;
  int k = s;
  for (; k + 4 <= e; k += 4) {
    int2 cv0 = __ldg(&g_cv[k]), cv1 = __ldg(&g_cv[k + 1]);
    int2 cv2 = __ldg(&g_cv[k + 2]), cv3 = __ldg(&g_cv[k + 3]);
    float2 f0 = __bfloat1622float2(__ldg(&x[(size_t)cv0.x * 32 + lane]));
    float2 f1 = __bfloat1622float2(__ldg(&x[(size_t)cv1.x * 32 + lane]));
    float2 f2 = __bfloat1622float2(__ldg(&x[(size_t)cv2.x * 32 + lane]));
    float2 f3 = __bfloat1622float2(__ldg(&x[(size_t)cv3.x * 32 + lane]));
    float v0 = __int_as_float(cv0.y), v1 = __int_as_float(cv1.y);
    float v2 = __int_as_float(cv2.y), v3 = __int_as_float(cv3.y);
    a0 += v0 * f0.x + v1 * f1.x + v2 * f2.x + v3 * f3.x;
    a1 += v0 * f0.y + v1 * f1.y + v2 * f2.y + v3 * f3.y;
  }
  for (; k < e; k++) {
    int2 cv = __ldg(&g_cv[k]);
    float2 f = __bfloat1622float2(__ldg(&x[(size_t)cv.x * 32 + lane]));
    float v = __int_as_float(cv.y);
    a0 += v * f.x;
    a1 += v * f.y;
  }
}

// hop-1 (proven core): writes clean + both perturbed views
__global__ __launch_bounds__(256)
void k_spmm3(const bf2* __restrict__ x,
             bf2* __restrict__ yB, bf2* __restrict__ yV1, bf2* __restrict__ yV2,
             uint32_t k10, uint32_t k11, uint32_t k20, uint32_t k21) {
  int w = (blockIdx.x * blockDim.x + threadIdx.x) >> 5;
  int lane = threadIdx.x & 31;
  if (w >= NTOT) return;
  float a0, a1;
  spmm_row(x, w, lane, a0, a1);
  size_t idx = (size_t)w * 32 + lane;
  yB[idx] = __float22bfloat162_rn(make_float2(a0, a1));
  float b0 = a0, b1 = a1;
  apply_perturb(b0, b1, k10, k11, w, lane);
  yV1[idx] = __float22bfloat162_rn(make_float2(b0, b1));
  float c0 = a0, c1 = a1;
  apply_perturb(c0, c1, k20, k21, w, lane);
  yV2[idx] = __float22bfloat162_rn(make_float2(c0, c1));
}

// ---------------- gather descriptor ----------------
struct GSet {
  const bf2* ego;
  const int* idx;
  int base;
  float* dst;
};
struct GArgs { GSet s[7]; };

// ---------------- fused hop-2: gather-1 head warps, then masked h2 list ------
// (dead warps past g_h2cnt land at the END of the grid and retire instantly)
__global__ __launch_bounds__(256)
void k_spmm_h2(const bf2* __restrict__ xB, const bf2* __restrict__ xV1,
               const bf2* __restrict__ xV2,
               bf2* __restrict__ yC0, bf2* __restrict__ yC1, bf2* __restrict__ yC2,
               uint32_t ka0, uint32_t ka1, uint32_t kb0, uint32_t kb1,
               GArgs ga) {
  int wi = (blockIdx.x * blockDim.x + threadIdx.x) >> 5;
  int lane = threadIdx.x & 31;
  if (wi < 7 * BATCH) {
    // gather-1 head: init batch accumulators from hop-1 outputs
    GSet g = ga.s[wi >> 12];
    int slot = wi & (BATCH - 1);
    int row = g.base + __ldg(&g.idx[slot]);
    float2 v = __bfloat1622float2(__ldg(&g.ego[(size_t)row * 32 + lane]));
    ((float2*)(g.dst + (size_t)slot * D))[lane] = v;
    return;
  }
  int li = wi - 7 * BATCH;
  if (li >= g_h2cnt) return;
  int w = __ldg(&g_h2list[li]);
  int s = g_rowptr[w], e = g_rowptr[w + 1];
  float a0 = 0.f, a1 = 0.f;
  float b0 = 0.f, b1 = 0.f;
  float c0 = 0.f, c1 = 0.f;
  int k = s;
  for (; k + 2 <= e; k += 2) {
    int2 cv0 = __ldg(&g_cv[k]), cv1 = __ldg(&g_cv[k + 1]);
    size_t o0 = (size_t)cv0.x * 32 + lane, o1 = (size_t)cv1.x * 32 + lane;
    float2 fB0 = __bfloat1622float2(__ldg(&xB[o0]));
    float2 fB1 = __bfloat1622float2(__ldg(&xB[o1]));
    float2 f10 = __bfloat1622float2(__ldg(&xV1[o0]));
    float2 f11 = __bfloat1622float2(__ldg(&xV1[o1]));
    float2 f20 = __bfloat1622float2(__ldg(&xV2[o0]));
    float2 f21 = __bfloat1622float2(__ldg(&xV2[o1]));
    float v0 = __int_as_float(cv0.y), v1 = __int_as_float(cv1.y);
    a0 += v0 * fB0.x + v1 * fB1.x;  a1 += v0 * fB0.y + v1 * fB1.y;
    b0 += v0 * f10.x + v1 * f11.x;  b1 += v0 * f10.y + v1 * f11.y;
    c0 += v0 * f20.x + v1 * f21.x;  c1 += v0 * f20.y + v1 * f21.y;
  }
  for (; k < e; k++) {
    int2 cv = __ldg(&g_cv[k]);
    size_t o = (size_t)cv.x * 32 + lane;
    float v = __int_as_float(cv.y);
    float2 fB = __bfloat1622float2(__ldg(&xB[o]));
    float2 f1 = __bfloat1622float2(__ldg(&xV1[o]));
    float2 f2 = __bfloat1622float2(__ldg(&xV2[o]));
    a0 += v * fB.x;  a1 += v * fB.y;
    b0 += v * f1.x;  b1 += v * f1.y;
    c0 += v * f2.x;  c1 += v * f2.y;
  }
  size_t idx = (size_t)w * 32 + lane;
  yC0[idx] = __float22bfloat162_rn(make_float2(a0, a1));
  apply_perturb(b0, b1, ka0, ka1, w, lane);
  yC1[idx] = __float22bfloat162_rn(make_float2(b0, b1));
  apply_perturb(c0, c1, kb0, kb1, w, lane);
  yC2[idx] = __float22bfloat162_rn(make_float2(c0, c1));
}

// ---------------- hop-3 list kernel + folded gather-2 + normalize ------------
struct H3Seg {
  const bf2* x;
  const int* idx;
  int base;
  float* dst;
  uint32_t k0, k1;
  int pert;  // pert!=0 => CL target => normalize after final add
};
struct H3Args { H3Seg s[7]; };

__global__ __launch_bounds__(256)
void k_hop3(H3Args ha) {
  int gw = (blockIdx.x * blockDim.x + threadIdx.x) >> 5;
  int lane = threadIdx.x & 31;
  if (gw >= 7 * BATCH) return;
  int seg = gw >> 12;
  int slot = gw & (BATCH - 1);
  H3Seg sg = ha.s[seg];
  int row = sg.base + __ldg(&sg.idx[slot]);
  float2 g2 = __bfloat1622float2(__ldg(&sg.x[(size_t)row * 32 + lane]));
  float a0, a1;
  spmm_row(sg.x, row, lane, a0, a1);
  if (sg.pert) apply_perturb(a0, a1, sg.k0, sg.k1, row, lane);
  float2* d = (float2*)(sg.dst + (size_t)slot * D) + lane;
  float2 o = *d;               // hop-1 value
  o.x += g2.x; o.y += g2.y;    // + hop-2
  o.x += a0;  o.y += a1;       // + hop-3
  if (sg.pert) {
    float ss = o.x * o.x + o.y * o.y;
#pragma unroll
    for (int of = 16; of; of >>= 1) ss += __shfl_xor_sync(0xffffffffu, ss, of);
    float inv = 1.0f / fmaxf(sqrtf(ss), 1e-12f);
    o.x *= inv; o.y *= inv;
  }
  *d = o;
}

// ---------------- BPR rec loss for one row (warp-collective) ----------------
__device__ __forceinline__ void rec_loss_row(int w, int lane) {
  const float s = 1.0f / 3.0f;
  float2 u = ((const float2*)g_acc[0])[(size_t)w * 32 + lane];
  float2 p = ((const float2*)g_acc[1])[(size_t)w * 32 + lane];
  float2 nn = ((const float2*)g_acc[2])[(size_t)w * 32 + lane];
  u.x *= s; u.y *= s; p.x *= s; p.y *= s; nn.x *= s; nn.y *= s;
  float ps = u.x * p.x + u.y * p.y;
  float ns = u.x * nn.x + u.y * nn.y;
  float u2 = u.x * u.x + u.y * u.y;
  float p2 = p.x * p.x + p.y * p.y;
#pragma unroll
  for (int o = 16; o; o >>= 1) {
    ps += __shfl_xor_sync(0xffffffffu, ps, o);
    ns += __shfl_xor_sync(0xffffffffu, ns, o);
    u2 += __shfl_xor_sync(0xffffffffu, u2, o);
    p2 += __shfl_xor_sync(0xffffffffu, p2, o);
  }
  if (lane == 0) {
    float dlt = ps - ns;
    float sig = 1.0f / (1.0f + __expf(-dlt));
    atomicAdd(&g_red[0], (double)(-logf(1e-5f + sig)));
    atomicAdd(&g_red[1], (double)u2);
    atomicAdd(&g_red[2], (double)p2);
  }
}

// ---------------- InfoNCE (z=0,1) + BPR rec loss (z=2) in one launch ----------
#define JSPLIT 16
#define IB 128
__global__ __launch_bounds__(128)
void k_nce_sim(const float* __restrict__ base1, const float* __restrict__ base2,
               float* __restrict__ ttlb, float* __restrict__ posbuf) {
  __shared__ float s2[IB * D];
  int z = blockIdx.z;
  if (z == 2) {
    int bid = blockIdx.x * JSPLIT + blockIdx.y;   // 0..511
    int warp = threadIdx.x >> 5;
    int lane = threadIdx.x & 31;
    int w0 = (bid * 4 + warp) * 2;
    rec_loss_row(w0, lane);
    rec_loss_row(w0 + 1, lane);
    return;
  }
  const float* n1 = base1 + (size_t)z * BATCH * D;  // z=0: v1u, z=1: v1i
  const float* n2 = base2 + (size_t)z * BATCH * D;  // z=0: v2u, z=1: v2i
  float* ttl = ttlb + z * BATCH;
  float* pos = posbuf + z * BATCH;
  int i = blockIdx.x * IB + threadIdx.x;
  ull r1[32];
  const ull* src = (const ull*)(n1 + (size_t)i * D);
#pragma unroll
  for (int q = 0; q < 32; q++) r1[q] = src[q];
  const int JCH = BATCH / JSPLIT;
  int j0 = blockIdx.y * JCH;
  float tt = 0.f, ps = 0.f;
  for (int jt = j0; jt < j0 + JCH; jt += IB) {
    __syncthreads();
#pragma unroll
    for (int t = 0; t < 16; t++)
      ((float4*)s2)[threadIdx.x + t * IB] =
          ((const float4*)(n2 + (size_t)jt * D))[threadIdx.x + t * IB];
    __syncthreads();
    for (int j = 0; j < IB; j++) {
      const ull* row = (const ull*)(s2 + j * D);
      ull acc0 = 0, acc1 = 0, acc2 = 0, acc3 = 0;
#pragma unroll
      for (int q = 0; q < 32; q += 4) {
        fma_f32x2(acc0, r1[q], row[q]);
        fma_f32x2(acc1, r1[q + 1], row[q + 1]);
        fma_f32x2(acc2, r1[q + 2], row[q + 2]);
        fma_f32x2(acc3, r1[q + 3], row[q + 3]);
      }
      float2 a0 = *(float2*)&acc0, a1 = *(float2*)&acc1;
      float2 a2 = *(float2*)&acc2, a3 = *(float2*)&acc3;
      float d = (a0.x + a0.y) + (a1.x + a1.y) + (a2.x + a2.y) + (a3.x + a3.y);
      float e = fast_exp(d * INV_TEMP);
      tt += e;
      if (jt + j == i) ps = e;
    }
  }
  atomicAdd(&ttl[i], tt);
  if ((int)blockIdx.y == (i / JCH)) pos[i] = ps;
}

// ---------------- fused NCE finalize + output scalar (single block) ----------
__global__ __launch_bounds__(1024)
void k_final2(float* out) {
  __shared__ double sh0[32], sh1[32];
  int t = threadIdx.x;
  double s0 = 0.0, s1 = 0.0;
  for (int i = t; i < BATCH; i += 1024) {
    s0 += (double)(-logf(g_posb[i] / g_ttl[i] + 1e-5f));
    s1 += (double)(-logf(g_posb[BATCH + i] / g_ttl[BATCH + i] + 1e-5f));
  }
#pragma unroll
  for (int o = 16; o; o >>= 1) {
    s0 += __shfl_xor_sync(0xffffffffu, s0, o);
    s1 += __shfl_xor_sync(0xffffffffu, s1, o);
  }
  if ((t & 31) == 0) { sh0[t >> 5] = s0; sh1[t >> 5] = s1; }
  __syncthreads();
  if (t < 32) {
    double w0 = sh0[t], w1 = sh1[t];
#pragma unroll
    for (int o = 16; o; o >>= 1) {
      w0 += __shfl_xor_sync(0xffffffffu, w0, o);
      w1 += __shfl_xor_sync(0xffffffffu, w1, o);
    }
    if (t == 0) {
      double rec = g_red[0] / (double)BATCH;
      double reg = DECAY * (sqrt(g_red[1]) + sqrt(g_red[2]));
      double cl = CL_RATE * (w0 / (double)BATCH + w1 / (double)BATCH);
      out[0] = (float)(rec + reg + cl);
    }
  }
}

// ---------------- host driver ----------------
extern "C" void kernel_launch(void* const* d_in, const int* in_sizes, int n_in,
                              void* d_out, int out_size) {
  const float* user = (const float*)d_in[0];
  const float* item = (const float*)d_in[1];
  const float* vals = (const float*)d_in[2];
  const int* rows = (const int*)d_in[3];
  const int* cols = (const int*)d_in[4];
  const int* users = (const int*)d_in[5];
  const int* pos = (const int*)d_in[6];
  const int* neg = (const int*)d_in[7];
  float* out = (float*)d_out;

  void* tmp;
  cudaGetSymbolAddress(&tmp, g_bufE);  bf2* E = (bf2*)tmp;
  cudaGetSymbolAddress(&tmp, g_bufB);  bf2* B = (bf2*)tmp;
  cudaGetSymbolAddress(&tmp, g_bufC);  bf2* C = (bf2*)tmp;
  cudaGetSymbolAddress(&tmp, g_bufC2); bf2* C2 = (bf2*)tmp;
  cudaGetSymbolAddress(&tmp, g_bufV1); bf2* V1 = (bf2*)tmp;
  cudaGetSymbolAddress(&tmp, g_bufV2); bf2* V2 = (bf2*)tmp;
  cudaGetSymbolAddress(&tmp, g_ttl);   float* ttl = (float*)tmp;
  cudaGetSymbolAddress(&tmp, g_posb);  float* posb = (float*)tmp;
  cudaGetSymbolAddress(&tmp, g_acc);   float* acc = (float*)tmp;
  float* accU = acc + 0 * BATCH * D;
  float* accP = acc + 1 * BATCH * D;
  float* accN = acc + 2 * BATCH * D;
  float* v1u = acc + 3 * BATCH * D;
  float* v1i = acc + 4 * BATCH * D;
  float* v2u = acc + 5 * BATCH * D;
  float* v2i = acc + 6 * BATCH * D;

  uint32_t K[2][3][2];
  uint32_t seeds[2] = {101u, 202u};
  for (int s = 0; s < 2; s++)
    for (int h = 0; h < 3; h++)
      tf2x32(0u, seeds[s], 0u, (uint32_t)h, K[s][h][0], K[s][h][1]);

  const int NB_NNZ = (NNZ + 255) / 256;
  const int SB = NTOT / 8;
  const int SB_H2 = (7 * BATCH + NTOT + 7) / 8;  // gather head + h2 warps

  // #1: convert + zero all state
  k_conv<<<(NTOT * 32 + 255) / 256, 256>>>(user, item);
  // #2-#5: CSR build + batch marking
  k_count<<<NB_NNZ, 256>>>(rows, users, pos, neg);
  k_scan1<<<NB_SCAN, 1024>>>();
  k_scan23<<<NB_SCAN, 1024>>>();
  k_scatter<<<NB_NNZ, 256>>>(rows, cols, vals);
  // #6-#7: hop-2 needed-rows list
  k_mscan1<<<NB_SCAN, 1024>>>();
  k_mcompact<<<NB_SCAN, 1024>>>();

  // #8: hop 1
  k_spmm3<<<SB, 256>>>(E, B, V1, V2, K[0][0][0], K[0][0][1], K[1][0][0], K[1][0][1]);

  // #9: hop 2 fused sweep (gather head + masked list; E free -> C0)
  {
    GArgs ga;
    ga.s[0] = {B, users, 0, accU};
    ga.s[1] = {B, pos, NU, accP};
    ga.s[2] = {B, neg, NU, accN};
    ga.s[3] = {V1, users, 0, v1u};
    ga.s[4] = {V1, pos, NU, v1i};
    ga.s[5] = {V2, users, 0, v2u};
    ga.s[6] = {V2, pos, NU, v2i};
    k_spmm_h2<<<SB_H2, 256>>>(B, V1, V2, E, C, C2,
                              K[0][1][0], K[0][1][1], K[1][1][0], K[1][1][1], ga);
  }

  // #10: hop 3 + folded gather-2 + normalize
  {
    H3Args ha;
    ha.s[0] = {E, users, 0, accU, 0u, 0u, 0};
    ha.s[1] = {E, pos, NU, accP, 0u, 0u, 0};
    ha.s[2] = {E, neg, NU, accN, 0u, 0u, 0};
    ha.s[3] = {C, users, 0, v1u, K[0][2][0], K[0][2][1], 1};
    ha.s[4] = {C, pos, NU, v1i, K[0][2][0], K[0][2][1], 1};
    ha.s[5] = {C2, users, 0, v2u, K[1][2][0], K[1][2][1], 1};
    ha.s[6] = {C2, pos, NU, v2i, K[1][2][0], K[1][2][1], 1};
    k_hop3<<<(7 * BATCH * 32) / 256, 256>>>(ha);
  }

  // #11-#12: losses (NCE z=0,1 + rec z=2) + finalize
  dim3 gsim(BATCH / IB, JSPLIT, 3);
  k_nce_sim<<<gsim, IB>>>(v1u, v2u, ttl, posb);
  k_final2<<<1, 1024>>>(out);
}

// round 16
// speedup vs baseline: 1.0182x; 1.0182x over previous
#include <cuda_runtime.h>
#include <cuda_bf16.h>
#include <cstdint>

#define NU    200000
#define NI    100000
#define NTOT  300000
#define D     64
#define NNZ   3000000
#define BATCH 4096
#define EPS_P    0.1f
#define INV_TEMP 5.0f
#define CL_RATE  0.5
#define DECAY    1e-4

typedef unsigned long long ull;
typedef __nv_bfloat162 bf2;

#define NB_SCAN 293  // ceil(NTOT/1024)

// ---------------- persistent device scratch ----------------
__device__ bf2  g_bufE[NTOT * 32];
__device__ bf2  g_bufB[NTOT * 32];
__device__ bf2  g_bufC[NTOT * 32];
__device__ bf2  g_bufC2[NTOT * 32];
__device__ bf2  g_bufV1[NTOT * 32];
__device__ bf2  g_bufV2[NTOT * 32];
__device__ int  g_rowptr[NTOT + 1];
__device__ int  g_cnt[NTOT];
__device__ int  g_bsum[512];
__device__ int2 g_cv[NNZ];
// hop-2 row masking
__device__ unsigned char g_isb_any[NTOT];  // row is any batch row
__device__ unsigned char g_isb_up[NTOT];   // row is users/pos batch row
__device__ int  g_mask[NTOT];              // C0 needed (all)
__device__ unsigned char g_mask2[NTOT];    // C1/C2 needed (users/pos reach)
__device__ int  g_mpos[NTOT];
__device__ int  g_bsum2[512];
__device__ int  g_h2list[NTOT];
__device__ int  g_h2cnt;
// 0:accU 1:accP 2:accN 3:v1u 4:v1i 5:v2u 6:v2i
__device__ float g_acc[7][BATCH * D];
__device__ float g_ttl[2 * BATCH];
__device__ float g_posb[2 * BATCH];
__device__ double g_red[8];

// ---------------- Threefry-2x32-20 (JAX schedule) ----------------
__host__ __device__ __forceinline__ uint32_t rotl32(uint32_t x, int r) {
#ifdef __CUDA_ARCH__
  return __funnelshift_l(x, x, r);
#else
  return (x << r) | (x >> (32 - r));
#endif
}

__host__ __device__ __forceinline__ void tf2x32(uint32_t k0, uint32_t k1,
                                                uint32_t x0, uint32_t x1,
                                                uint32_t& o0, uint32_t& o1) {
  uint32_t ks2 = k0 ^ k1 ^ 0x1BD11BDAu;
  x0 += k0; x1 += k1;
#define TFR(r) { x0 += x1; x1 = rotl32(x1, r); x1 ^= x0; }
  TFR(13) TFR(15) TFR(26) TFR(6)
  x0 += k1;  x1 += ks2 + 1u;
  TFR(17) TFR(29) TFR(16) TFR(24)
  x0 += ks2; x1 += k0 + 2u;
  TFR(13) TFR(15) TFR(26) TFR(6)
  x0 += k0;  x1 += k1 + 3u;
  TFR(17) TFR(29) TFR(16) TFR(24)
  x0 += k1;  x1 += ks2 + 4u;
  TFR(13) TFR(15) TFR(26) TFR(6)
  x0 += ks2; x1 += k0 + 5u;
#undef TFR
  o0 = x0; o1 = x1;
}

__device__ __forceinline__ float tf_uniform(uint32_t k0, uint32_t k1, uint32_t j) {
  uint32_t a, b;
  tf2x32(k0, k1, 0u, j, a, b);
  uint32_t bits = a ^ b;
  return __uint_as_float((bits >> 9) | 0x3F800000u) - 1.0f;
}

__device__ __forceinline__ void apply_perturb(float& a0, float& a1,
                                              uint32_t k0, uint32_t k1,
                                              int row, int lane) {
  uint32_t j = (uint32_t)row * 64u + (uint32_t)(2 * lane);
  float u0 = tf_uniform(k0, k1, j);
  float u1 = tf_uniform(k0, k1, j + 1u);
  float ss = u0 * u0 + u1 * u1;
#pragma unroll
  for (int o = 16; o; o >>= 1) ss += __shfl_xor_sync(0xffffffffu, ss, o);
  float sc = EPS_P / fmaxf(sqrtf(ss), 1e-12f);
  float s0 = (a0 > 0.f ? 1.f : (a0 < 0.f ? -1.f : 0.f));
  float s1 = (a1 > 0.f ? 1.f : (a1 < 0.f ? -1.f : 0.f));
  a0 = fmaf(s0 * sc, u0, a0);
  a1 = fmaf(s1 * sc, u1, a1);
}

// ---------------- fast exp on FMA pipe ----------------
__device__ __forceinline__ float fast_exp(float x) {
  float y = x * 1.44269504088896341f;
  int ni = __float2int_rn(y);
  float f = y - (float)ni;
  float p = 0.0013333558146428443f;
  p = fmaf(p, f, 0.009618129107628477f);
  p = fmaf(p, f, 0.05550410866482158f);
  p = fmaf(p, f, 0.2402265069591007f);
  p = fmaf(p, f, 0.6931471805599453f);
  p = fmaf(p, f, 1.0f);
  float s = __int_as_float((ni + 127) << 23);
  return p * s;
}

__device__ __forceinline__ void fma_f32x2(ull& d, ull a, ull b) {
  asm("fma.rn.f32x2 %0, %1, %2, %0;" : "+l"(d) : "l"(a), "l"(b));
}

// warp-shuffle inclusive scan within a 1024-thread block.
__device__ __forceinline__ int block_incl_scan(int v, int t, int* sh32) {
  int lane = t & 31, wid = t >> 5;
#pragma unroll
  for (int o = 1; o < 32; o <<= 1) {
    int n = __shfl_up_sync(0xffffffffu, v, o);
    if (lane >= o) v += n;
  }
  if (lane == 31) sh32[wid] = v;
  __syncthreads();
  if (wid == 0) {
    int w = sh32[lane];
#pragma unroll
    for (int o = 1; o < 32; o <<= 1) {
      int n = __shfl_up_sync(0xffffffffu, w, o);
      if (lane >= o) w += n;
    }
    sh32[lane] = w;
  }
  __syncthreads();
  if (wid > 0) v += sh32[wid - 1];
  return v;
}

// ---------------- launch 1: convert ego0 + zero all state ----------------
__global__ void k_conv(const float* __restrict__ u, const float* __restrict__ it) {
  int i = blockIdx.x * blockDim.x + threadIdx.x;
  if (i < NTOT) {
    g_cnt[i] = 0; g_mask[i] = 0; g_mask2[i] = 0;
    g_isb_any[i] = 0; g_isb_up[i] = 0;
  }
  if (i < 2 * BATCH) g_ttl[i] = 0.f;
  if (i < 8) g_red[i] = 0.0;
  if (i >= NTOT * 32) return;
  const float2* src = (i < NU * 32) ? ((const float2*)u + i)
                                    : ((const float2*)it + (i - NU * 32));
  g_bufE[i] = __float22bfloat162_rn(*src);
}

// ---------------- CSR count + batch-row marking ----------------
__global__ void k_count(const int* __restrict__ rows,
                        const int* __restrict__ users, const int* __restrict__ pos,
                        const int* __restrict__ neg) {
  int i = blockIdx.x * blockDim.x + threadIdx.x;
  if (i < NNZ) atomicAdd(&g_cnt[rows[i]], 1);
  if (i < BATCH) {
    int ru = __ldg(&users[i]);
    int rp = NU + __ldg(&pos[i]);
    int rn = NU + __ldg(&neg[i]);
    g_isb_any[ru] = 1; g_isb_any[rp] = 1; g_isb_any[rn] = 1;
    g_isb_up[ru] = 1;  g_isb_up[rp] = 1;
    g_mask[ru] = 1; g_mask[rp] = 1; g_mask[rn] = 1;
    g_mask2[ru] = 1; g_mask2[rp] = 1;
  }
}

__global__ void k_scan1() {
  __shared__ int sh32[32];
  int gid = blockIdx.x * 1024 + threadIdx.x;
  int v = (gid < NTOT) ? g_cnt[gid] : 0;
  v = block_incl_scan(v, threadIdx.x, sh32);
  if (gid < NTOT) g_rowptr[gid + 1] = v;
  if (threadIdx.x == 1023) g_bsum[blockIdx.x] = v;
}

// fused scan2+scan3+cursor
__global__ void k_scan23() {
  __shared__ int sh[32];
  int t = threadIdx.x;
  int bid = blockIdx.x;
  int v = (t < bid && t < NB_SCAN) ? g_bsum[t] : 0;
#pragma unroll
  for (int o = 16; o; o >>= 1) v += __shfl_xor_sync(0xffffffffu, v, o);
  if ((t & 31) == 0) sh[t >> 5] = v;
  __syncthreads();
  if (t < 32) {
    int w = sh[t];
#pragma unroll
    for (int o = 16; o; o >>= 1) w += __shfl_xor_sync(0xffffffffu, w, o);
    if (t == 0) sh[0] = w;
  }
  __syncthreads();
  int pref = sh[0];
  int gid = bid * 1024 + t;
  if (gid < NTOT) {
    int cntv = g_cnt[gid];
    int rp_next = g_rowptr[gid + 1] + pref;
    g_rowptr[gid + 1] = rp_next;
    g_cnt[gid] = rp_next - cntv;  // cursor = row start
    if (gid == 0) g_rowptr[0] = 0;
  }
}

// scatter + neighbor marking (flags built in k_count)
__global__ void k_scatter(const int* __restrict__ rows, const int* __restrict__ cols,
                          const float* __restrict__ vals) {
  int i = blockIdx.x * blockDim.x + threadIdx.x;
  if (i >= NNZ) return;
  int r = rows[i];
  int c = cols[i];
  int p = atomicAdd(&g_cnt[r], 1);
  g_cv[p] = make_int2(c, __float_as_int(vals[i]));
  if (g_isb_any[r]) {
    g_mask[c] = 1;
    if (g_isb_up[r]) g_mask2[c] = 1;
  }
}

__global__ void k_mscan1() {
  __shared__ int sh32[32];
  int gid = blockIdx.x * 1024 + threadIdx.x;
  int v = (gid < NTOT) ? g_mask[gid] : 0;
  v = block_incl_scan(v, threadIdx.x, sh32);
  if (gid < NTOT) g_mpos[gid] = v;  // inclusive
  if (threadIdx.x == 1023) g_bsum2[blockIdx.x] = v;
}

// compact + total count (dual reduction: prefix + total)
__global__ void k_mcompact() {
  __shared__ int shp[32], sht[32];
  int t = threadIdx.x;
  int bid = blockIdx.x;
  int va = (t < NB_SCAN) ? g_bsum2[t] : 0;
  int vp = (t < bid) ? va : 0;
#pragma unroll
  for (int o = 16; o; o >>= 1) {
    va += __shfl_xor_sync(0xffffffffu, va, o);
    vp += __shfl_xor_sync(0xffffffffu, vp, o);
  }
  if ((t & 31) == 0) { shp[t >> 5] = vp; sht[t >> 5] = va; }
  __syncthreads();
  if (t < 32) {
    int wp = shp[t], wa = sht[t];
#pragma unroll
    for (int o = 16; o; o >>= 1) {
      wp += __shfl_xor_sync(0xffffffffu, wp, o);
      wa += __shfl_xor_sync(0xffffffffu, wa, o);
    }
    if (t == 0) { shp[0] = wp; sht[0] = wa; }
  }
  __syncthreads();
  int pref = shp[0];
  int gid = bid * 1024 + t;
  if (gid < NTOT && g_mask[gid])
    g_h2list[g_mpos[gid] - 1 + pref] = gid;
  if (bid == 0 && t == 0) g_h2cnt = sht[0];
}

// ---------------- SPMM core (single input, unroll 4 — proven) ----------------
__device__ __forceinline__ void spmm_row(const bf2* __restrict__ x,
                                         int w, int lane, float& a0, float& a1) {
  int s = g_rowptr[w], e = g_rowptr[w + 1];
  a0 = 0.f; a1 = 0.f;
  int k = s;
  for (; k + 4 <= e; k += 4) {
    int2 cv0 = __ldg(&g_cv[k]), cv1 = __ldg(&g_cv[k + 1]);
    int2 cv2 = __ldg(&g_cv[k + 2]), cv3 = __ldg(&g_cv[k + 3]);
    float2 f0 = __bfloat1622float2(__ldg(&x[(size_t)cv0.x * 32 + lane]));
    float2 f1 = __bfloat1622float2(__ldg(&x[(size_t)cv1.x * 32 + lane]));
    float2 f2 = __bfloat1622float2(__ldg(&x[(size_t)cv2.x * 32 + lane]));
    float2 f3 = __bfloat1622float2(__ldg(&x[(size_t)cv3.x * 32 + lane]));
    float v0 = __int_as_float(cv0.y), v1 = __int_as_float(cv1.y);
    float v2 = __int_as_float(cv2.y), v3 = __int_as_float(cv3.y);
    a0 += v0 * f0.x + v1 * f1.x + v2 * f2.x + v3 * f3.x;
    a1 += v0 * f0.y + v1 * f1.y + v2 * f2.y + v3 * f3.y;
  }
  for (; k < e; k++) {
    int2 cv = __ldg(&g_cv[k]);
    float2 f = __bfloat1622float2(__ldg(&x[(size_t)cv.x * 32 + lane]));
    float v = __int_as_float(cv.y);
    a0 += v * f.x;
    a1 += v * f.y;
  }
}

// hop-1 (proven core): writes clean + both perturbed views
__global__ __launch_bounds__(256)
void k_spmm3(const bf2* __restrict__ x,
             bf2* __restrict__ yB, bf2* __restrict__ yV1, bf2* __restrict__ yV2,
             uint32_t k10, uint32_t k11, uint32_t k20, uint32_t k21) {
  int w = (blockIdx.x * blockDim.x + threadIdx.x) >> 5;
  int lane = threadIdx.x & 31;
  if (w >= NTOT) return;
  float a0, a1;
  spmm_row(x, w, lane, a0, a1);
  size_t idx = (size_t)w * 32 + lane;
  yB[idx] = __float22bfloat162_rn(make_float2(a0, a1));
  float b0 = a0, b1 = a1;
  apply_perturb(b0, b1, k10, k11, w, lane);
  yV1[idx] = __float22bfloat162_rn(make_float2(b0, b1));
  float c0 = a0, c1 = a1;
  apply_perturb(c0, c1, k20, k21, w, lane);
  yV2[idx] = __float22bfloat162_rn(make_float2(c0, c1));
}

// ---------------- gather descriptor ----------------
struct GSet {
  const bf2* ego;
  const int* idx;
  int base;
  float* dst;
};
struct GArgs { GSet s[7]; };

// ---------------- fused hop-2: gather head, then masked h2 list ----------
// Rows without mask2 skip the V1/V2 views entirely (never read downstream).
__global__ __launch_bounds__(256)
void k_spmm_h2(const bf2* __restrict__ xB, const bf2* __restrict__ xV1,
               const bf2* __restrict__ xV2,
               bf2* __restrict__ yC0, bf2* __restrict__ yC1, bf2* __restrict__ yC2,
               uint32_t ka0, uint32_t ka1, uint32_t kb0, uint32_t kb1,
               GArgs ga) {
  int wi = (blockIdx.x * blockDim.x + threadIdx.x) >> 5;
  int lane = threadIdx.x & 31;
  if (wi < 7 * BATCH) {
    GSet g = ga.s[wi >> 12];
    int slot = wi & (BATCH - 1);
    int row = g.base + __ldg(&g.idx[slot]);
    float2 v = __bfloat1622float2(__ldg(&g.ego[(size_t)row * 32 + lane]));
    ((float2*)(g.dst + (size_t)slot * D))[lane] = v;
    return;
  }
  int li = wi - 7 * BATCH;
  if (li >= g_h2cnt) return;
  int w = __ldg(&g_h2list[li]);
  int s = g_rowptr[w], e = g_rowptr[w + 1];
  size_t idx = (size_t)w * 32 + lane;
  if (g_mask2[w]) {
    float a0 = 0.f, a1 = 0.f;
    float b0 = 0.f, b1 = 0.f;
    float c0 = 0.f, c1 = 0.f;
    int k = s;
    for (; k + 2 <= e; k += 2) {
      int2 cv0 = __ldg(&g_cv[k]), cv1 = __ldg(&g_cv[k + 1]);
      size_t o0 = (size_t)cv0.x * 32 + lane, o1 = (size_t)cv1.x * 32 + lane;
      float2 fB0 = __bfloat1622float2(__ldg(&xB[o0]));
      float2 fB1 = __bfloat1622float2(__ldg(&xB[o1]));
      float2 f10 = __bfloat1622float2(__ldg(&xV1[o0]));
      float2 f11 = __bfloat1622float2(__ldg(&xV1[o1]));
      float2 f20 = __bfloat1622float2(__ldg(&xV2[o0]));
      float2 f21 = __bfloat1622float2(__ldg(&xV2[o1]));
      float v0 = __int_as_float(cv0.y), v1 = __int_as_float(cv1.y);
      a0 += v0 * fB0.x + v1 * fB1.x;  a1 += v0 * fB0.y + v1 * fB1.y;
      b0 += v0 * f10.x + v1 * f11.x;  b1 += v0 * f10.y + v1 * f11.y;
      c0 += v0 * f20.x + v1 * f21.x;  c1 += v0 * f20.y + v1 * f21.y;
    }
    for (; k < e; k++) {
      int2 cv = __ldg(&g_cv[k]);
      size_t o = (size_t)cv.x * 32 + lane;
      float v = __int_as_float(cv.y);
      float2 fB = __bfloat1622float2(__ldg(&xB[o]));
      float2 f1 = __bfloat1622float2(__ldg(&xV1[o]));
      float2 f2 = __bfloat1622float2(__ldg(&xV2[o]));
      a0 += v * fB.x;  a1 += v * fB.y;
      b0 += v * f1.x;  b1 += v * f1.y;
      c0 += v * f2.x;  c1 += v * f2.y;
    }
    yC0[idx] = __float22bfloat162_rn(make_float2(a0, a1));
    apply_perturb(b0, b1, ka0, ka1, w, lane);
    yC1[idx] = __float22bfloat162_rn(make_float2(b0, b1));
    apply_perturb(c0, c1, kb0, kb1, w, lane);
    yC2[idx] = __float22bfloat162_rn(make_float2(c0, c1));
  } else {
    // neg-only reach: only the clean view C0 is ever read downstream
    float a0, a1;
    spmm_row(xB, w, lane, a0, a1);
    yC0[idx] = __float22bfloat162_rn(make_float2(a0, a1));
  }
}

// ---------------- hop-3 list kernel + folded gather-2 + normalize ------------
struct H3Seg {
  const bf2* x;
  const int* idx;
  int base;
  float* dst;
  uint32_t k0, k1;
  int pert;  // pert!=0 => CL target => normalize after final add
};
struct H3Args { H3Seg s[7]; };

__global__ __launch_bounds__(256)
void k_hop3(H3Args ha) {
  int gw = (blockIdx.x * blockDim.x + threadIdx.x) >> 5;
  int lane = threadIdx.x & 31;
  if (gw >= 7 * BATCH) return;
  int seg = gw >> 12;
  int slot = gw & (BATCH - 1);
  H3Seg sg = ha.s[seg];
  int row = sg.base + __ldg(&sg.idx[slot]);
  float2 g2 = __bfloat1622float2(__ldg(&sg.x[(size_t)row * 32 + lane]));
  float a0, a1;
  spmm_row(sg.x, row, lane, a0, a1);
  if (sg.pert) apply_perturb(a0, a1, sg.k0, sg.k1, row, lane);
  float2* d = (float2*)(sg.dst + (size_t)slot * D) + lane;
  float2 o = *d;               // hop-1 value
  o.x += g2.x; o.y += g2.y;    // + hop-2
  o.x += a0;  o.y += a1;       // + hop-3
  if (sg.pert) {
    float ss = o.x * o.x + o.y * o.y;
#pragma unroll
    for (int of = 16; of; of >>= 1) ss += __shfl_xor_sync(0xffffffffu, ss, of);
    float inv = 1.0f / fmaxf(sqrtf(ss), 1e-12f);
    o.x *= inv; o.y *= inv;
  }
  *d = o;
}

// ---------------- BPR rec loss for one row (warp-collective) ----------------
__device__ __forceinline__ void rec_loss_row(int w, int lane) {
  const float s = 1.0f / 3.0f;
  float2 u = ((const float2*)g_acc[0])[(size_t)w * 32 + lane];
  float2 p = ((const float2*)g_acc[1])[(size_t)w * 32 + lane];
  float2 nn = ((const float2*)g_acc[2])[(size_t)w * 32 + lane];
  u.x *= s; u.y *= s; p.x *= s; p.y *= s; nn.x *= s; nn.y *= s;
  float ps = u.x * p.x + u.y * p.y;
  float ns = u.x * nn.x + u.y * nn.y;
  float u2 = u.x * u.x + u.y * u.y;
  float p2 = p.x * p.x + p.y * p.y;
#pragma unroll
  for (int o = 16; o; o >>= 1) {
    ps += __shfl_xor_sync(0xffffffffu, ps, o);
    ns += __shfl_xor_sync(0xffffffffu, ns, o);
    u2 += __shfl_xor_sync(0xffffffffu, u2, o);
    p2 += __shfl_xor_sync(0xffffffffu, p2, o);
  }
  if (lane == 0) {
    float dlt = ps - ns;
    float sig = 1.0f / (1.0f + __expf(-dlt));
    atomicAdd(&g_red[0], (double)(-logf(1e-5f + sig)));
    atomicAdd(&g_red[1], (double)u2);
    atomicAdd(&g_red[2], (double)p2);
  }
}

// ---------------- InfoNCE (z=0,1) + BPR rec loss (z=2) in one launch ----------
#define JSPLIT 16
#define IB 128
__global__ __launch_bounds__(128)
void k_nce_sim(const float* __restrict__ base1, const float* __restrict__ base2,
               float* __restrict__ ttlb, float* __restrict__ posbuf) {
  __shared__ float s2[IB * D];
  int z = blockIdx.z;
  if (z == 2) {
    int bid = blockIdx.x * JSPLIT + blockIdx.y;   // 0..511
    int warp = threadIdx.x >> 5;
    int lane = threadIdx.x & 31;
    int w0 = (bid * 4 + warp) * 2;
    rec_loss_row(w0, lane);
    rec_loss_row(w0 + 1, lane);
    return;
  }
  const float* n1 = base1 + (size_t)z * BATCH * D;  // z=0: v1u, z=1: v1i
  const float* n2 = base2 + (size_t)z * BATCH * D;  // z=0: v2u, z=1: v2i
  float* ttl = ttlb + z * BATCH;
  float* pos = posbuf + z * BATCH;
  int i = blockIdx.x * IB + threadIdx.x;
  ull r1[32];
  const ull* src = (const ull*)(n1 + (size_t)i * D);
#pragma unroll
  for (int q = 0; q < 32; q++) r1[q] = src[q];
  const int JCH = BATCH / JSPLIT;
  int j0 = blockIdx.y * JCH;
  float tt = 0.f, ps = 0.f;
  for (int jt = j0; jt < j0 + JCH; jt += IB) {
    __syncthreads();
#pragma unroll
    for (int t = 0; t < 16; t++)
      ((float4*)s2)[threadIdx.x + t * IB] =
          ((const float4*)(n2 + (size_t)jt * D))[threadIdx.x + t * IB];
    __syncthreads();
    for (int j = 0; j < IB; j++) {
      const ull* row = (const ull*)(s2 + j * D);
      ull acc0 = 0, acc1 = 0, acc2 = 0, acc3 = 0;
#pragma unroll
      for (int q = 0; q < 32; q += 4) {
        fma_f32x2(acc0, r1[q], row[q]);
        fma_f32x2(acc1, r1[q + 1], row[q + 1]);
        fma_f32x2(acc2, r1[q + 2], row[q + 2]);
        fma_f32x2(acc3, r1[q + 3], row[q + 3]);
      }
      float2 a0 = *(float2*)&acc0, a1 = *(float2*)&acc1;
      float2 a2 = *(float2*)&acc2, a3 = *(float2*)&acc3;
      float d = (a0.x + a0.y) + (a1.x + a1.y) + (a2.x + a2.y) + (a3.x + a3.y);
      float e = fast_exp(d * INV_TEMP);
      tt += e;
      if (jt + j == i) ps = e;
    }
  }
  atomicAdd(&ttl[i], tt);
  if ((int)blockIdx.y == (i / JCH)) pos[i] = ps;
}

// ---------------- fused NCE finalize + output scalar (single block) ----------
__global__ __launch_bounds__(1024)
void k_final2(float* out) {
  __shared__ double sh0[32], sh1[32];
  int t = threadIdx.x;
  double s0 = 0.0, s1 = 0.0;
  for (int i = t; i < BATCH; i += 1024) {
    s0 += (double)(-logf(g_posb[i] / g_ttl[i] + 1e-5f));
    s1 += (double)(-logf(g_posb[BATCH + i] / g_ttl[BATCH + i] + 1e-5f));
  }
#pragma unroll
  for (int o = 16; o; o >>= 1) {
    s0 += __shfl_xor_sync(0xffffffffu, s0, o);
    s1 += __shfl_xor_sync(0xffffffffu, s1, o);
  }
  if ((t & 31) == 0) { sh0[t >> 5] = s0; sh1[t >> 5] = s1; }
  __syncthreads();
  if (t < 32) {
    double w0 = sh0[t], w1 = sh1[t];
#pragma unroll
    for (int o = 16; o; o >>= 1) {
      w0 += __shfl_xor_sync(0xffffffffu, w0, o);
      w1 += __shfl_xor_sync(0xffffffffu, w1, o);
    }
    if (t == 0) {
      double rec = g_red[0] / (double)BATCH;
      double reg = DECAY * (sqrt(g_red[1]) + sqrt(g_red[2]));
      double cl = CL_RATE * (w0 / (double)BATCH + w1 / (double)BATCH);
      out[0] = (float)(rec + reg + cl);
    }
  }
}

// ---------------- host driver ----------------
extern "C" void kernel_launch(void* const* d_in, const int* in_sizes, int n_in,
                              void* d_out, int out_size) {
  const float* user = (const float*)d_in[0];
  const float* item = (const float*)d_in[1];
  const float* vals = (const float*)d_in[2];
  const int* rows = (const int*)d_in[3];
  const int* cols = (const int*)d_in[4];
  const int* users = (const int*)d_in[5];
  const int* pos = (const int*)d_in[6];
  const int* neg = (const int*)d_in[7];
  float* out = (float*)d_out;

  void* tmp;
  cudaGetSymbolAddress(&tmp, g_bufE);  bf2* E = (bf2*)tmp;
  cudaGetSymbolAddress(&tmp, g_bufB);  bf2* B = (bf2*)tmp;
  cudaGetSymbolAddress(&tmp, g_bufC);  bf2* C = (bf2*)tmp;
  cudaGetSymbolAddress(&tmp, g_bufC2); bf2* C2 = (bf2*)tmp;
  cudaGetSymbolAddress(&tmp, g_bufV1); bf2* V1 = (bf2*)tmp;
  cudaGetSymbolAddress(&tmp, g_bufV2); bf2* V2 = (bf2*)tmp;
  cudaGetSymbolAddress(&tmp, g_ttl);   float* ttl = (float*)tmp;
  cudaGetSymbolAddress(&tmp, g_posb);  float* posb = (float*)tmp;
  cudaGetSymbolAddress(&tmp, g_acc);   float* acc = (float*)tmp;
  float* accU = acc + 0 * BATCH * D;
  float* accP = acc + 1 * BATCH * D;
  float* accN = acc + 2 * BATCH * D;
  float* v1u = acc + 3 * BATCH * D;
  float* v1i = acc + 4 * BATCH * D;
  float* v2u = acc + 5 * BATCH * D;
  float* v2i = acc + 6 * BATCH * D;

  uint32_t K[2][3][2];
  uint32_t seeds[2] = {101u, 202u};
  for (int s = 0; s < 2; s++)
    for (int h = 0; h < 3; h++)
      tf2x32(0u, seeds[s], 0u, (uint32_t)h, K[s][h][0], K[s][h][1]);

  const int NB_NNZ = (NNZ + 255) / 256;
  const int SB = NTOT / 8;
  const int SB_H2 = (7 * BATCH + NTOT + 7) / 8;  // gather head + h2 warps

  // #1: convert + zero all state
  k_conv<<<(NTOT * 32 + 255) / 256, 256>>>(user, item);
  // #2-#5: CSR build + batch marking
  k_count<<<NB_NNZ, 256>>>(rows, users, pos, neg);
  k_scan1<<<NB_SCAN, 1024>>>();
  k_scan23<<<NB_SCAN, 1024>>>();
  k_scatter<<<NB_NNZ, 256>>>(rows, cols, vals);
  // #6-#7: hop-2 needed-rows list
  k_mscan1<<<NB_SCAN, 1024>>>();
  k_mcompact<<<NB_SCAN, 1024>>>();

  // #8: hop 1
  k_spmm3<<<SB, 256>>>(E, B, V1, V2, K[0][0][0], K[0][0][1], K[1][0][0], K[1][0][1]);

  // #9: hop 2 fused sweep (gather head + masked list; E free -> C0)
  {
    GArgs ga;
    ga.s[0] = {B, users, 0, accU};
    ga.s[1] = {B, pos, NU, accP};
    ga.s[2] = {B, neg, NU, accN};
    ga.s[3] = {V1, users, 0, v1u};
    ga.s[4] = {V1, pos, NU, v1i};
    ga.s[5] = {V2, users, 0, v2u};
    ga.s[6] = {V2, pos, NU, v2i};
    k_spmm_h2<<<SB_H2, 256>>>(B, V1, V2, E, C, C2,
                              K[0][1][0], K[0][1][1], K[1][1][0], K[1][1][1], ga);
  }

  // #10: hop 3 + folded gather-2 + normalize
  {
    H3Args ha;
    ha.s[0] = {E, users, 0, accU, 0u, 0u, 0};
    ha.s[1] = {E, pos, NU, accP, 0u, 0u, 0};
    ha.s[2] = {E, neg, NU, accN, 0u, 0u, 0};
    ha.s[3] = {C, users, 0, v1u, K[0][2][0], K[0][2][1], 1};
    ha.s[4] = {C, pos, NU, v1i, K[0][2][0], K[0][2][1], 1};
    ha.s[5] = {C2, users, 0, v2u, K[1][2][0], K[1][2][1], 1};
    ha.s[6] = {C2, pos, NU, v2i, K[1][2][0], K[1][2][1], 1};
    k_hop3<<<(7 * BATCH * 32) / 256, 256>>>(ha);
  }

  // #11-#12: losses (NCE z=0,1 + rec z=2) + finalize
  dim3 gsim(BATCH / IB, JSPLIT, 3);
  k_nce_sim<<<gsim, IB>>>(v1u, v2u, ttl, posb);
  k_final2<<<1, 1024>>>(out);
}